// round 10
// baseline (speedup 1.0000x reference)
#include <cuda_runtime.h>
#include <cstdint>
#include <cstddef>
#include <math.h>

#define LABEL_DIM 173
#define VECT_DIM  32
#define NBLOCKS   1184
#define NTHREADS  256
#define PROW      36          // padded partial row: 32 colsums + 1 sumsq + pad

// Per-block partials + completion counter. Partials fully overwritten each
// launch; the counter returns to 0 at the end of every launch (last block
// resets it) -> graph-replay deterministic.
__device__ float    g_partial[NBLOCKS * PROW];
__device__ unsigned g_count = 0;

// ---------------------------------------------------------------------------
// Fused kernel. Hot loop is the EXACT round-5 shape (plain loads, no cache
// hints, MLP from warp count alone): that configuration measured ~5.6-6 TB/s.
// __launch_bounds__(256, 8) keeps regs at 32 -> 8 CTAs/SM (97% occ, proven
// round 8). __ldcs REMOVED: A/B evidence across rounds 5..9 shows the .cs
// hint costs ~40% of DRAM bandwidth on sm_100a for this LDG.128 stream.
//
// Lane->column mapping: grid*block and the grid stride are multiples of 8,
// so a thread's float4 index i always satisfies i % 8 == tid % 8:
// lane l owns columns 4*(l%8) .. 4*(l%8)+3.
// ---------------------------------------------------------------------------
__global__ void __launch_bounds__(NTHREADS, 8)
vd_fused_kernel(const float4* __restrict__ x, long long n4,
                const float* __restrict__ means,
                float* __restrict__ out) {
    const unsigned lane = threadIdx.x & 31u;
    const unsigned wid  = threadIdx.x >> 5;

    // ---- Phase 1: streaming reduce (round-5 proven loop) ----
    float4 acc = make_float4(0.f, 0.f, 0.f, 0.f);
    float  sq  = 0.f;

    long long stride = (long long)gridDim.x * blockDim.x;
    for (long long i = (long long)blockIdx.x * blockDim.x + threadIdx.x;
         i < n4; i += stride) {
        float4 v = x[i];
        acc.x += v.x; acc.y += v.y; acc.z += v.z; acc.w += v.w;
        sq += v.x * v.x + v.y * v.y + v.z * v.z + v.w * v.w;
    }

    // sumsq: full warp tree
    #pragma unroll
    for (int off = 16; off >= 1; off >>= 1)
        sq += __shfl_xor_sync(0xFFFFFFFFu, sq, off);

    // column sums: lanes l, l^8, l^16, l^24 own the same 4-column group.
    #pragma unroll
    for (int off = 16; off >= 8; off >>= 1) {
        acc.x += __shfl_xor_sync(0xFFFFFFFFu, acc.x, off);
        acc.y += __shfl_xor_sync(0xFFFFFFFFu, acc.y, off);
        acc.z += __shfl_xor_sync(0xFFFFFFFFu, acc.z, off);
        acc.w += __shfl_xor_sync(0xFFFFFFFFu, acc.w, off);
    }

    __shared__ float s_warp[NTHREADS / 32][PROW];
    if (lane < 8) {
        s_warp[wid][lane * 4 + 0] = acc.x;
        s_warp[wid][lane * 4 + 1] = acc.y;
        s_warp[wid][lane * 4 + 2] = acc.z;
        s_warp[wid][lane * 4 + 3] = acc.w;
    }
    if (lane == 0) s_warp[wid][32] = sq;
    __syncthreads();

    if (threadIdx.x < 33) {
        float v = 0.f;
        #pragma unroll
        for (int w = 0; w < NTHREADS / 32; w++) v += s_warp[w][threadIdx.x];
        g_partial[blockIdx.x * PROW + threadIdx.x] = v;
    }

    // ---- Last-block election ----
    __shared__ bool s_last;
    __threadfence();                     // partials visible before counter bump
    if (threadIdx.x == 0) {
        unsigned prev = atomicAdd(&g_count, 1u);
        s_last = (prev == NBLOCKS - 1);
    }
    __syncthreads();
    if (!s_last) return;

    // ---- Phase 2 (last block only): combine L2-hot partials, distances, argmin ----
    if (threadIdx.x == 0) g_count = 0;   // reset for next graph replay

    __shared__ float s_part[8][VECT_DIM];
    __shared__ float s_xsum[VECT_DIM];
    __shared__ float s_sumsq;
    __shared__ float s_dist[NTHREADS];
    __shared__ int   s_idx[NTHREADS];

    int t = threadIdx.x;
    int r = t >> 5;                      // 0..7
    int c = t & 31;                      // 0..31

    {
        float a = 0.f;
        for (int b = r; b < NBLOCKS; b += 8)
            a += g_partial[b * PROW + c];
        s_part[r][c] = a;
    }
    if (t < 32) {
        float sqp = 0.f;
        for (int b = t; b < NBLOCKS; b += 32)
            sqp += g_partial[b * PROW + 32];
        #pragma unroll
        for (int off = 16; off >= 1; off >>= 1)
            sqp += __shfl_xor_sync(0xFFFFFFFFu, sqp, off);
        if (t == 0) s_sumsq = sqp;
    }
    __syncthreads();

    if (t < VECT_DIM) {
        float v = 0.f;
        #pragma unroll
        for (int w = 0; w < 8; w++) v += s_part[w][t];
        s_xsum[t] = v;
    }
    __syncthreads();

    float xnorm = sqrtf(s_sumsq);

    float dist = INFINITY;
    if (t < LABEL_DIM) {
        const float* m = means + (size_t)t * VECT_DIM;
        float dot = 0.f, ysq = 0.f;
        #pragma unroll
        for (int d = 0; d < VECT_DIM; d++) {
            float mv = m[d];
            dot += s_xsum[d] * mv;
            ysq += mv * mv;
        }
        dist = 1.0f - dot / (xnorm * sqrtf(ysq));
    }
    s_dist[t] = (t < LABEL_DIM) ? dist : INFINITY;
    s_idx[t]  = (t < LABEL_DIM) ? t : 0;
    __syncthreads();

    for (int s2 = NTHREADS / 2; s2 >= 1; s2 >>= 1) {
        if (t < s2) {
            float a = s_dist[t], b = s_dist[t + s2];
            bool take = (b < a) || (isnan(a) && !isnan(b));
            if (take) { s_dist[t] = b; s_idx[t] = s_idx[t + s2]; }
        }
        __syncthreads();
    }
    if (t == 0) out[0] = (float)s_idx[0];   // __output__ dtype is float32
}

// ---------------------------------------------------------------------------
// Scalar fallback path (unaligned x — never expected with cudaMalloc bufs).
// ---------------------------------------------------------------------------
__global__ void vd_reduce_scalar(const float* __restrict__ x, long long n) {
    const unsigned lane = threadIdx.x & 31u;
    const unsigned wid  = threadIdx.x >> 5;

    float acc = 0.f, sq = 0.f;
    long long stride = (long long)gridDim.x * blockDim.x;
    for (long long i = (long long)blockIdx.x * blockDim.x + threadIdx.x;
         i < n; i += stride) {
        float v = x[i];
        acc += v; sq += v * v;
    }
    #pragma unroll
    for (int off = 16; off >= 1; off >>= 1)
        sq += __shfl_xor_sync(0xFFFFFFFFu, sq, off);

    __shared__ float s_warp[NTHREADS / 32][PROW];
    s_warp[wid][lane] = acc;           // lane l owns column l (stride % 32 == 0)
    if (lane == 0) s_warp[wid][32] = sq;
    __syncthreads();

    if (threadIdx.x < 33) {
        float v = 0.f;
        #pragma unroll
        for (int w = 0; w < NTHREADS / 32; w++) v += s_warp[w][threadIdx.x];
        g_partial[blockIdx.x * PROW + threadIdx.x] = v;
    }
}

__global__ void vd_finalize_kernel(const float* __restrict__ means,
                                   float* __restrict__ out) {
    __shared__ float s_part[8][VECT_DIM];
    __shared__ float s_xsum[VECT_DIM];
    __shared__ float s_sumsq;
    __shared__ float s_dist[NTHREADS];
    __shared__ int   s_idx[NTHREADS];

    int t = threadIdx.x;
    int r = t >> 5, c = t & 31;
    {
        float a = 0.f;
        for (int b = r; b < NBLOCKS; b += 8)
            a += g_partial[b * PROW + c];
        s_part[r][c] = a;
    }
    if (t < 32) {
        float sqp = 0.f;
        for (int b = t; b < NBLOCKS; b += 32)
            sqp += g_partial[b * PROW + 32];
        #pragma unroll
        for (int off = 16; off >= 1; off >>= 1)
            sqp += __shfl_xor_sync(0xFFFFFFFFu, sqp, off);
        if (t == 0) s_sumsq = sqp;
    }
    __syncthreads();
    if (t < VECT_DIM) {
        float v = 0.f;
        #pragma unroll
        for (int w = 0; w < 8; w++) v += s_part[w][t];
        s_xsum[t] = v;
    }
    __syncthreads();

    float xnorm = sqrtf(s_sumsq);
    float dist = INFINITY;
    if (t < LABEL_DIM) {
        const float* m = means + (size_t)t * VECT_DIM;
        float dot = 0.f, ysq = 0.f;
        #pragma unroll
        for (int d = 0; d < VECT_DIM; d++) {
            float mv = m[d];
            dot += s_xsum[d] * mv; ysq += mv * mv;
        }
        dist = 1.0f - dot / (xnorm * sqrtf(ysq));
    }
    s_dist[t] = (t < LABEL_DIM) ? dist : INFINITY;
    s_idx[t]  = (t < LABEL_DIM) ? t : 0;
    __syncthreads();
    for (int s = NTHREADS / 2; s >= 1; s >>= 1) {
        if (t < s) {
            float a = s_dist[t], b = s_dist[t + s];
            bool take = (b < a) || (isnan(a) && !isnan(b));
            if (take) { s_dist[t] = b; s_idx[t] = s_idx[t + s]; }
        }
        __syncthreads();
    }
    if (t == 0) out[0] = (float)s_idx[0];
}

// ---------------------------------------------------------------------------
extern "C" void kernel_launch(void* const* d_in, const int* in_sizes, int n_in,
                              void* d_out, int out_size) {
    // x = largest input; means = the input with exactly 173*32 elements.
    int xi = 0;
    for (int i = 1; i < n_in; i++)
        if (in_sizes[i] > in_sizes[xi]) xi = i;
    int mi = -1;
    for (int i = 0; i < n_in; i++)
        if (i != xi && in_sizes[i] == LABEL_DIM * VECT_DIM) { mi = i; break; }
    if (mi < 0) { mi = (xi == 0 && n_in > 1) ? 1 : 0; }

    const float* x     = (const float*)d_in[xi];
    const float* means = (const float*)d_in[mi];
    long long n = (long long)in_sizes[xi];

    bool aligned16 = ((((unsigned long long)(size_t)x) & 15ull) == 0) &&
                     (n % 4 == 0);
    if (aligned16) {
        vd_fused_kernel<<<NBLOCKS, NTHREADS>>>((const float4*)x, n / 4,
                                               means, (float*)d_out);
    } else {
        vd_reduce_scalar<<<NBLOCKS, NTHREADS>>>(x, n);
        vd_finalize_kernel<<<1, NTHREADS>>>(means, (float*)d_out);
    }
}

// round 11
// speedup vs baseline: 1.0321x; 1.0321x over previous
#include <cuda_runtime.h>
#include <cstdint>
#include <cstddef>
#include <math.h>

#define LABEL_DIM 173
#define VECT_DIM  32
#define NBLOCKS   1024
#define NTHREADS  256
#define GROUP     (NTHREADS * 8)   // float4s per unrolled block-iteration
#define PROW      36               // padded partial row: 32 colsums + 1 sumsq

// Per-block partials + completion counter. Partials fully overwritten each
// launch; the counter returns to 0 at the end of every launch (last block
// resets it) -> graph-replay deterministic.
__device__ float    g_partial[NBLOCKS * PROW];
__device__ unsigned g_count = 0;

// ---------------------------------------------------------------------------
// Fused kernel, block-CONTIGUOUS partitioning. Each block owns one
// contiguous chunk (multiple of GROUP float4s) and streams it sequentially
// in 8-deep unrolled groups: consecutive warp instructions touch adjacent
// 512B lines -> DRAM row-buffer friendly, unlike the 4.7MB-stride
// grid-stride pattern that plateaued at ~3.6 TB/s in rounds 5-10.
//
// Lane->column invariant: chunk base, GROUP, and the 256-thread step are all
// multiples of 8 float4s, so i % 8 == threadIdx.x % 8 always: lane l owns
// columns 4*(l%8) .. 4*(l%8)+3.
// ---------------------------------------------------------------------------
__global__ void __launch_bounds__(NTHREADS, 8)
vd_fused_kernel(const float4* __restrict__ x, long long n4,
                const float* __restrict__ means,
                float* __restrict__ out) {
    const unsigned lane = threadIdx.x & 31u;
    const unsigned wid  = threadIdx.x >> 5;

    // Per-block contiguous chunk, rounded up to a multiple of GROUP.
    const long long per_block =
        ((n4 + gridDim.x - 1) / gridDim.x + GROUP - 1) / GROUP * GROUP;
    const long long base = (long long)blockIdx.x * per_block;
    const long long end  = (base + per_block < n4) ? base + per_block : n4;

    float4 acc = make_float4(0.f, 0.f, 0.f, 0.f);
    float  sq0 = 0.f, sq1 = 0.f;

    long long i = base + threadIdx.x;
    // Main loop: 8 independent loads per iteration, sequential 4KB steps.
    for (; i + 7 * NTHREADS < end; i += GROUP) {
        float4 v0 = x[i + 0 * NTHREADS];
        float4 v1 = x[i + 1 * NTHREADS];
        float4 v2 = x[i + 2 * NTHREADS];
        float4 v3 = x[i + 3 * NTHREADS];
        float4 v4 = x[i + 4 * NTHREADS];
        float4 v5 = x[i + 5 * NTHREADS];
        float4 v6 = x[i + 6 * NTHREADS];
        float4 v7 = x[i + 7 * NTHREADS];

        acc.x += v0.x; acc.y += v0.y; acc.z += v0.z; acc.w += v0.w;
        sq0 += v0.x * v0.x + v0.y * v0.y + v0.z * v0.z + v0.w * v0.w;
        acc.x += v1.x; acc.y += v1.y; acc.z += v1.z; acc.w += v1.w;
        sq1 += v1.x * v1.x + v1.y * v1.y + v1.z * v1.z + v1.w * v1.w;
        acc.x += v2.x; acc.y += v2.y; acc.z += v2.z; acc.w += v2.w;
        sq0 += v2.x * v2.x + v2.y * v2.y + v2.z * v2.z + v2.w * v2.w;
        acc.x += v3.x; acc.y += v3.y; acc.z += v3.z; acc.w += v3.w;
        sq1 += v3.x * v3.x + v3.y * v3.y + v3.z * v3.z + v3.w * v3.w;
        acc.x += v4.x; acc.y += v4.y; acc.z += v4.z; acc.w += v4.w;
        sq0 += v4.x * v4.x + v4.y * v4.y + v4.z * v4.z + v4.w * v4.w;
        acc.x += v5.x; acc.y += v5.y; acc.z += v5.z; acc.w += v5.w;
        sq1 += v5.x * v5.x + v5.y * v5.y + v5.z * v5.z + v5.w * v5.w;
        acc.x += v6.x; acc.y += v6.y; acc.z += v6.z; acc.w += v6.w;
        sq0 += v6.x * v6.x + v6.y * v6.y + v6.z * v6.z + v6.w * v6.w;
        acc.x += v7.x; acc.y += v7.y; acc.z += v7.z; acc.w += v7.w;
        sq1 += v7.x * v7.x + v7.y * v7.y + v7.z * v7.z + v7.w * v7.w;
    }
    // Tail (empty for the 2^23-float4 production shape).
    for (; i < end; i += NTHREADS) {
        float4 v = x[i];
        acc.x += v.x; acc.y += v.y; acc.z += v.z; acc.w += v.w;
        sq0 += v.x * v.x + v.y * v.y + v.z * v.z + v.w * v.w;
    }
    float sq = sq0 + sq1;

    // sumsq: full warp tree
    #pragma unroll
    for (int off = 16; off >= 1; off >>= 1)
        sq += __shfl_xor_sync(0xFFFFFFFFu, sq, off);

    // column sums: lanes l, l^8, l^16, l^24 own the same 4-column group.
    #pragma unroll
    for (int off = 16; off >= 8; off >>= 1) {
        acc.x += __shfl_xor_sync(0xFFFFFFFFu, acc.x, off);
        acc.y += __shfl_xor_sync(0xFFFFFFFFu, acc.y, off);
        acc.z += __shfl_xor_sync(0xFFFFFFFFu, acc.z, off);
        acc.w += __shfl_xor_sync(0xFFFFFFFFu, acc.w, off);
    }

    __shared__ float s_warp[NTHREADS / 32][PROW];
    if (lane < 8) {
        s_warp[wid][lane * 4 + 0] = acc.x;
        s_warp[wid][lane * 4 + 1] = acc.y;
        s_warp[wid][lane * 4 + 2] = acc.z;
        s_warp[wid][lane * 4 + 3] = acc.w;
    }
    if (lane == 0) s_warp[wid][32] = sq;
    __syncthreads();

    if (threadIdx.x < 33) {
        float v = 0.f;
        #pragma unroll
        for (int w = 0; w < NTHREADS / 32; w++) v += s_warp[w][threadIdx.x];
        g_partial[blockIdx.x * PROW + threadIdx.x] = v;
    }

    // ---- Last-block election ----
    __shared__ bool s_last;
    __threadfence();                     // partials visible before counter bump
    if (threadIdx.x == 0) {
        unsigned prev = atomicAdd(&g_count, 1u);
        s_last = (prev == gridDim.x - 1);
    }
    __syncthreads();
    if (!s_last) return;

    // ---- Phase 2 (last block only): combine L2-hot partials, distances, argmin ----
    if (threadIdx.x == 0) g_count = 0;   // reset for next graph replay

    __shared__ float s_part[8][VECT_DIM];
    __shared__ float s_xsum[VECT_DIM];
    __shared__ float s_sumsq;
    __shared__ float s_dist[NTHREADS];
    __shared__ int   s_idx[NTHREADS];

    int t = threadIdx.x;
    int r = t >> 5;                      // 0..7
    int c = t & 31;                      // 0..31

    {
        float a = 0.f;
        for (int b = r; b < NBLOCKS; b += 8)
            a += g_partial[b * PROW + c];
        s_part[r][c] = a;
    }
    if (t < 32) {
        float sqp = 0.f;
        for (int b = t; b < NBLOCKS; b += 32)
            sqp += g_partial[b * PROW + 32];
        #pragma unroll
        for (int off = 16; off >= 1; off >>= 1)
            sqp += __shfl_xor_sync(0xFFFFFFFFu, sqp, off);
        if (t == 0) s_sumsq = sqp;
    }
    __syncthreads();

    if (t < VECT_DIM) {
        float v = 0.f;
        #pragma unroll
        for (int w = 0; w < 8; w++) v += s_part[w][t];
        s_xsum[t] = v;
    }
    __syncthreads();

    float xnorm = sqrtf(s_sumsq);

    float dist = INFINITY;
    if (t < LABEL_DIM) {
        const float* m = means + (size_t)t * VECT_DIM;
        float dot = 0.f, ysq = 0.f;
        #pragma unroll
        for (int d = 0; d < VECT_DIM; d++) {
            float mv = m[d];
            dot += s_xsum[d] * mv;
            ysq += mv * mv;
        }
        dist = 1.0f - dot / (xnorm * sqrtf(ysq));
    }
    s_dist[t] = (t < LABEL_DIM) ? dist : INFINITY;
    s_idx[t]  = (t < LABEL_DIM) ? t : 0;
    __syncthreads();

    for (int s2 = NTHREADS / 2; s2 >= 1; s2 >>= 1) {
        if (t < s2) {
            float a = s_dist[t], b = s_dist[t + s2];
            bool take = (b < a) || (isnan(a) && !isnan(b));
            if (take) { s_dist[t] = b; s_idx[t] = s_idx[t + s2]; }
        }
        __syncthreads();
    }
    if (t == 0) out[0] = (float)s_idx[0];   // __output__ dtype is float32
}

// ---------------------------------------------------------------------------
// Scalar fallback path (unaligned x — never expected with cudaMalloc bufs).
// ---------------------------------------------------------------------------
__global__ void vd_reduce_scalar(const float* __restrict__ x, long long n) {
    const unsigned lane = threadIdx.x & 31u;
    const unsigned wid  = threadIdx.x >> 5;

    float acc = 0.f, sq = 0.f;
    long long stride = (long long)gridDim.x * blockDim.x;
    for (long long i = (long long)blockIdx.x * blockDim.x + threadIdx.x;
         i < n; i += stride) {
        float v = x[i];
        acc += v; sq += v * v;
    }
    #pragma unroll
    for (int off = 16; off >= 1; off >>= 1)
        sq += __shfl_xor_sync(0xFFFFFFFFu, sq, off);

    __shared__ float s_warp[NTHREADS / 32][PROW];
    s_warp[wid][lane] = acc;           // lane l owns column l (stride % 32 == 0)
    if (lane == 0) s_warp[wid][32] = sq;
    __syncthreads();

    if (threadIdx.x < 33) {
        float v = 0.f;
        #pragma unroll
        for (int w = 0; w < NTHREADS / 32; w++) v += s_warp[w][threadIdx.x];
        g_partial[blockIdx.x * PROW + threadIdx.x] = v;
    }
}

__global__ void vd_finalize_kernel(const float* __restrict__ means,
                                   float* __restrict__ out) {
    __shared__ float s_part[8][VECT_DIM];
    __shared__ float s_xsum[VECT_DIM];
    __shared__ float s_sumsq;
    __shared__ float s_dist[NTHREADS];
    __shared__ int   s_idx[NTHREADS];

    int t = threadIdx.x;
    int r = t >> 5, c = t & 31;
    {
        float a = 0.f;
        for (int b = r; b < NBLOCKS; b += 8)
            a += g_partial[b * PROW + c];
        s_part[r][c] = a;
    }
    if (t < 32) {
        float sqp = 0.f;
        for (int b = t; b < NBLOCKS; b += 32)
            sqp += g_partial[b * PROW + 32];
        #pragma unroll
        for (int off = 16; off >= 1; off >>= 1)
            sqp += __shfl_xor_sync(0xFFFFFFFFu, sqp, off);
        if (t == 0) s_sumsq = sqp;
    }
    __syncthreads();
    if (t < VECT_DIM) {
        float v = 0.f;
        #pragma unroll
        for (int w = 0; w < 8; w++) v += s_part[w][t];
        s_xsum[t] = v;
    }
    __syncthreads();

    float xnorm = sqrtf(s_sumsq);
    float dist = INFINITY;
    if (t < LABEL_DIM) {
        const float* m = means + (size_t)t * VECT_DIM;
        float dot = 0.f, ysq = 0.f;
        #pragma unroll
        for (int d = 0; d < VECT_DIM; d++) {
            float mv = m[d];
            dot += s_xsum[d] * mv; ysq += mv * mv;
        }
        dist = 1.0f - dot / (xnorm * sqrtf(ysq));
    }
    s_dist[t] = (t < LABEL_DIM) ? dist : INFINITY;
    s_idx[t]  = (t < LABEL_DIM) ? t : 0;
    __syncthreads();
    for (int s = NTHREADS / 2; s >= 1; s >>= 1) {
        if (t < s) {
            float a = s_dist[t], b = s_dist[t + s];
            bool take = (b < a) || (isnan(a) && !isnan(b));
            if (take) { s_dist[t] = b; s_idx[t] = s_idx[t + s]; }
        }
        __syncthreads();
    }
    if (t == 0) out[0] = (float)s_idx[0];
}

// ---------------------------------------------------------------------------
extern "C" void kernel_launch(void* const* d_in, const int* in_sizes, int n_in,
                              void* d_out, int out_size) {
    // x = largest input; means = the input with exactly 173*32 elements.
    int xi = 0;
    for (int i = 1; i < n_in; i++)
        if (in_sizes[i] > in_sizes[xi]) xi = i;
    int mi = -1;
    for (int i = 0; i < n_in; i++)
        if (i != xi && in_sizes[i] == LABEL_DIM * VECT_DIM) { mi = i; break; }
    if (mi < 0) { mi = (xi == 0 && n_in > 1) ? 1 : 0; }

    const float* x     = (const float*)d_in[xi];
    const float* means = (const float*)d_in[mi];
    long long n = (long long)in_sizes[xi];

    bool aligned16 = ((((unsigned long long)(size_t)x) & 15ull) == 0) &&
                     (n % 4 == 0);
    if (aligned16) {
        vd_fused_kernel<<<NBLOCKS, NTHREADS>>>((const float4*)x, n / 4,
                                               means, (float*)d_out);
    } else {
        vd_reduce_scalar<<<NBLOCKS, NTHREADS>>>(x, n);
        vd_finalize_kernel<<<1, NTHREADS>>>(means, (float*)d_out);
    }
}